// round 14
// baseline (speedup 1.0000x reference)
#include <cuda_runtime.h>
#include <cuda_bf16.h>
#include <cstdint>
#include <math.h>

#define NB_C   100000
#define SZ_D   64
#define SZ_B   1024
#define BM     128
#define BN     128
#define CB     ((NB_C + BN - 1) / BN)   // 782 class blocks
#define N_PAD  (CB * BN - NB_C)         // 96 pad classes, each contributes exactly 1.0
#define GRIDX  38                       // 38 x 8 = 304 CTAs = 2 per SM (152 SMs)
#define LOG2E  1.4426950408889634f

// ---- device scratch (no allocations allowed) ----
__device__ float          g_Pn [(size_t)NB_C * SZ_D];  // normalized proxies fp32 (combine only)
__device__ __nv_bfloat16  g_Pb [(size_t)NB_C * SZ_D];  // normalized proxies bf16 (GEMM B)
__device__ __nv_bfloat16  g_Xb [(size_t)SZ_B * SZ_D];  // xs bf16 (GEMM A)
__device__ float          g_psq[NB_C];                 // sum(Pn^2), exact fp32
__device__ float          g_partial[(size_t)SZ_B * CB * 2];   // [row][cb][half]
__device__ float          g_persample[SZ_B];
__device__ int            g_ys[SZ_B];

// ---------------- PTX helpers ----------------
__device__ __forceinline__ void ldsm_x4(unsigned& r0, unsigned& r1, unsigned& r2, unsigned& r3,
                                        unsigned saddr) {
    asm volatile("ldmatrix.sync.aligned.m8n8.x4.shared.b16 {%0,%1,%2,%3}, [%4];"
                 : "=r"(r0), "=r"(r1), "=r"(r2), "=r"(r3) : "r"(saddr));
}
__device__ __forceinline__ void mma_bf16(float* d, const unsigned* a, const unsigned* b) {
    asm("mma.sync.aligned.m16n8k16.row.col.f32.bf16.bf16.f32 "
        "{%0,%1,%2,%3}, {%4,%5,%6,%7}, {%8,%9}, {%0,%1,%2,%3};"
        : "+f"(d[0]), "+f"(d[1]), "+f"(d[2]), "+f"(d[3])
        : "r"(a[0]), "r"(a[1]), "r"(a[2]), "r"(a[3]), "r"(b[0]), "r"(b[1]));
}
__device__ __forceinline__ void cp_async16(unsigned dst, const void* src, unsigned sz) {
    asm volatile("cp.async.cg.shared.global [%0], [%1], 16, %2;"
                 :: "r"(dst), "l"(src), "r"(sz) : "memory");
}
__device__ __forceinline__ void cp_commit() { asm volatile("cp.async.commit_group;" ::: "memory"); }
template<int N> __device__ __forceinline__ void cp_wait() {
    asm volatile("cp.async.wait_group %0;" :: "n"(N) : "memory");
}
__device__ __forceinline__ float ex2(float x) {
    float y; asm("ex2.approx.ftz.f32 %0, %1;" : "=f"(y) : "f"(x)); return y;
}

// ============ Kernel 0: decode labels (int32 vs int64 robust) ============
__global__ void decode_ys_kernel(const int* __restrict__ ys32) {
    __shared__ int nonzero_odd;
    const int tid = threadIdx.x;           // 1024 threads
    if (tid == 0) nonzero_odd = 0;
    __syncthreads();
    if (tid < SZ_B / 2) {
        if (ys32[2 * tid + 1] != 0) atomicOr(&nonzero_odd, 1);
    }
    __syncthreads();
    if (nonzero_odd) g_ys[tid] = ys32[tid];
    else             g_ys[tid] = (int)((const long long*)ys32)[tid];
}

// ============ Kernel 0b: xs -> bf16 ============
__global__ void cvt_xs_kernel(const float* __restrict__ xs) {
    int i = blockIdx.x * 256 + threadIdx.x;          // 16384 float4 groups
    float4 v = *(const float4*)(xs + (size_t)i * 4);
    __nv_bfloat162 lo = __floats2bfloat162_rn(v.x, v.y);
    __nv_bfloat162 hi = __floats2bfloat162_rn(v.z, v.w);
    *(unsigned*)(g_Xb + (size_t)i * 4)     = *(unsigned*)&lo;
    *(unsigned*)(g_Xb + (size_t)i * 4 + 2) = *(unsigned*)&hi;
}

// ================= Kernel A: row-normalize proxies (fp32 + bf16 out) =================
__global__ void normalize_kernel(const float* __restrict__ proxies) {
    int row  = blockIdx.x * 8 + (threadIdx.x >> 5);
    int lane = threadIdx.x & 31;
    if (row >= NB_C) return;
    const float2 v = *(const float2*)(proxies + (size_t)row * SZ_D + lane * 2);
    float s = v.x * v.x + v.y * v.y;
    #pragma unroll
    for (int o = 16; o; o >>= 1) s += __shfl_xor_sync(0xffffffffu, s, o);
    float norm = sqrtf(s);
    float inv  = 1.0f / fmaxf(norm, 1e-12f);
    float2 w; w.x = v.x * inv; w.y = v.y * inv;
    *(float2*)(g_Pn + (size_t)row * SZ_D + lane * 2) = w;
    __nv_bfloat162 wb = __floats2bfloat162_rn(w.x, w.y);
    *(unsigned*)(g_Pb + (size_t)row * SZ_D + lane * 2) = *(unsigned*)&wb;
    if (lane == 0) g_psq[row] = s * inv * inv;
}

// ===== Kernel B: persistent bf16 mma GEMM, 8 warps as 4(M) x 2(N) =====
// Warp tile 32x64: acc = 64 regs (2 CTAs/SM kept) while B smem redundancy drops
// 8x -> 4x and A -> 2x. The two N-half warps write separate g_partial slots;
// combine_kernel sums both halves. A loaded once; B streams via 2 buffers.
__global__ void __launch_bounds__(256, 2)
gemm_lse_kernel(void) {
    __shared__ __align__(1024) __nv_bfloat16 As[BM * 64];        // 16 KB
    __shared__ __align__(1024) __nv_bfloat16 Bs[2][BN * 64];     // 32 KB

    const int tid  = threadIdx.x;          // 256
    const int lane = tid & 31;
    const int wid  = tid >> 5;             // 0..7
    const int wm   = wid >> 1;             // 0..3 (M group)
    const int wn   = wid & 1;              // 0..1 (N half)
    const int qr   = lane >> 2;            // 0..7
    const int qc   = lane & 3;             // 0..3
    const int row0 = blockIdx.y * BM;
    const int mb   = wm * 32;              // warp's 32 rows
    const int nb   = wn * 64;              // warp's 64 cols

    const unsigned As_a = (unsigned)__cvta_generic_to_shared(As);
    const unsigned Bs_a = (unsigned)__cvta_generic_to_shared(Bs);

    // -- A fill (once): 1024 16B chunks over 256 threads --
    #pragma unroll
    for (int i = 0; i < 4; i++) {
        int idx = tid + i * 256;
        int r = idx >> 3, c = idx & 7;
        cp_async16(As_a + r * 128 + ((c ^ (r & 7)) << 4),
                   g_Xb + (size_t)(row0 + r) * SZ_D + c * 8, 16u);
    }
    // -- first B prefetch into buffer 0 --
    #pragma unroll
    for (int i = 0; i < 4; i++) {
        int idx = tid + i * 256;
        int r = idx >> 3, c = idx & 7;
        int cls = blockIdx.x * BN + r;
        cp_async16(Bs_a + r * 128 + ((c ^ (r & 7)) << 4),
                   g_Pb + (size_t)cls * SZ_D + c * 8, (cls < NB_C) ? 16u : 0u);
    }
    cp_commit();

    // ldmatrix lane address components
    const unsigned rAl   = (lane & 15);                   // + mb + mf*16
    const unsigned cAoff = (lane >> 4);
    const unsigned rBl   = ((lane >> 4) << 3) + (lane & 7);
    const unsigned cBoff = ((lane >> 3) & 1);

    int buf = 0;
    for (int cb = blockIdx.x; cb < CB; cb += GRIDX) {
        const int next = cb + GRIDX;
        if (next < CB) {
            #pragma unroll
            for (int i = 0; i < 4; i++) {
                int idx = tid + i * 256;
                int r = idx >> 3, c = idx & 7;
                int cls = next * BN + r;
                cp_async16(Bs_a + (buf ^ 1) * (BN * 128) + r * 128 + ((c ^ (r & 7)) << 4),
                           g_Pb + (size_t)cls * SZ_D + c * 8, (cls < NB_C) ? 16u : 0u);
            }
            cp_commit();
            cp_wait<1>();
        } else {
            cp_wait<0>();
        }
        __syncthreads();

        const unsigned Bb = Bs_a + buf * (BN * 128);
        float acc[2][8][4];
        #pragma unroll
        for (int mf = 0; mf < 2; mf++)
            #pragma unroll
            for (int nf = 0; nf < 8; nf++)
                #pragma unroll
                for (int c = 0; c < 4; c++) acc[mf][nf][c] = 0.0f;

        #pragma unroll
        for (int s = 0; s < 4; s++) {                    // 4 k16-steps
            unsigned a[2][4], b[8][2];
            unsigned cA = s * 2 + cAoff;
            #pragma unroll
            for (int mf = 0; mf < 2; mf++) {
                unsigned r = mb + mf * 16 + rAl;
                ldsm_x4(a[mf][0], a[mf][1], a[mf][2], a[mf][3],
                        As_a + r * 128 + (((cA ^ (r & 7)) & 7) << 4));
            }
            #pragma unroll
            for (int g = 0; g < 4; g++) {                // 4 x4 loads cover 64 cols
                unsigned r = nb + g * 16 + rBl;
                unsigned cB = s * 2 + cBoff;
                ldsm_x4(b[2 * g][0], b[2 * g][1], b[2 * g + 1][0], b[2 * g + 1][1],
                        Bb + r * 128 + (((cB ^ (r & 7)) & 7) << 4));
            }
            #pragma unroll
            for (int mf = 0; mf < 2; mf++)
                #pragma unroll
                for (int nf = 0; nf < 8; nf++)
                    mma_bf16(acc[mf][nf], a[mf], b[nf]);
        }

        // -- epilogue: e = exp2(2*log2e*acc - psq*log2e), no masks --
        const float TWO_L2E = 2.0f * LOG2E;
        #pragma unroll
        for (int mf = 0; mf < 2; mf++) {
            float s0 = 0.0f, s1 = 0.0f;
            #pragma unroll
            for (int nf = 0; nf < 8; nf++) {
                int cls0 = cb * BN + nb + nf * 8 + qc * 2;   // even; pair all-or-none
                float2 q = (cls0 < NB_C) ? *(const float2*)(g_psq + cls0)
                                         : make_float2(0.0f, 0.0f);
                float q0 = q.x * LOG2E, q1 = q.y * LOG2E;
                s0 += ex2(fmaf(TWO_L2E, acc[mf][nf][0], -q0));
                s0 += ex2(fmaf(TWO_L2E, acc[mf][nf][1], -q1));
                s1 += ex2(fmaf(TWO_L2E, acc[mf][nf][2], -q0));
                s1 += ex2(fmaf(TWO_L2E, acc[mf][nf][3], -q1));
            }
            #pragma unroll
            for (int o = 1; o <= 2; o <<= 1) {
                s0 += __shfl_xor_sync(0xffffffffu, s0, o);
                s1 += __shfl_xor_sync(0xffffffffu, s1, o);
            }
            if (qc == 0) {
                int r = row0 + mb + mf * 16 + qr;
                g_partial[((size_t)r * CB + cb) * 2 + wn]       = s0;
                g_partial[((size_t)(r + 8) * CB + cb) * 2 + wn] = s1;
            }
        }
        __syncthreads();        // everyone done with buf before it is refilled
        buf ^= 1;
    }
}

// ===== Kernel C: combine partials (2 halves), subtract pads + positive term =====
__global__ void combine_kernel(const float* __restrict__ xs) {
    const int row = blockIdx.x;
    const int tid = threadIdx.x;   // 256 threads
    const int y   = g_ys[row];

    float S = 0.0f;
    for (int p = tid; p < CB; p += 256) {
        float2 h = *(const float2*)(g_partial + ((size_t)row * CB + p) * 2);
        S += h.x + h.y;
    }

    float d = 0.0f;
    if (tid < SZ_D) d = xs[(size_t)row * SZ_D + tid] * g_Pn[(size_t)y * SZ_D + tid];

    #pragma unroll
    for (int o = 16; o; o >>= 1) {
        S += __shfl_xor_sync(0xffffffffu, S, o);
        d += __shfl_xor_sync(0xffffffffu, d, o);
    }
    __shared__ float sS[8], sD[8];
    int w = tid >> 5, lane = tid & 31;
    if (lane == 0) { sS[w] = S; sD[w] = d; }
    __syncthreads();
    if (tid == 0) {
        float St = 0.0f, Dt = 0.0f;
        #pragma unroll
        for (int k = 0; k < 8; k++) { St += sS[k]; Dt += sD[k]; }
        float psq_y = g_psq[y];
        // remove the 96 pad ones (exact) and the positive-class exp term
        float Sneg = St - (float)N_PAD - __expf(fmaf(2.0f, Dt, -psq_y));
        // per_sample = d_pos + log_n ; the ||x||^2 terms cancel exactly
        g_persample[row] = psq_y - 2.0f * Dt + logf(Sneg);
    }
}

// ===== Kernel D: mean over batch =====
__global__ void mean_kernel(float* __restrict__ out) {
    const int tid = threadIdx.x;   // 1024
    float v = g_persample[tid];
    #pragma unroll
    for (int o = 16; o; o >>= 1) v += __shfl_xor_sync(0xffffffffu, v, o);
    __shared__ float s[32];
    int w = tid >> 5, lane = tid & 31;
    if (lane == 0) s[w] = v;
    __syncthreads();
    if (tid < 32) {
        float t = s[tid];
        #pragma unroll
        for (int o = 16; o; o >>= 1) t += __shfl_xor_sync(0xffffffffu, t, o);
        if (tid == 0) out[0] = t * (1.0f / (float)SZ_B);
    }
}

extern "C" void kernel_launch(void* const* d_in, const int* in_sizes, int n_in,
                              void* d_out, int out_size) {
    const float* xs      = (const float*)d_in[0];
    const int*   ys_raw  = (const int*)d_in[1];
    const float* proxies = (const float*)d_in[2];
    float*       out     = (float*)d_out;

    decode_ys_kernel<<<1, SZ_B>>>(ys_raw);
    cvt_xs_kernel<<<(SZ_B * SZ_D / 4) / 256, 256>>>(xs);
    normalize_kernel<<<(NB_C + 7) / 8, 256>>>(proxies);
    gemm_lse_kernel<<<dim3(GRIDX, SZ_B / BM), 256>>>();
    combine_kernel<<<SZ_B, 256>>>(xs);
    mean_kernel<<<1, SZ_B>>>(out);
}